// round 14
// baseline (speedup 1.0000x reference)
#include <cuda_runtime.h>
#include <cstdint>

// SSIM over 11x11 patches — persistent double-buffered bulk-TMA pipeline.
// img_pred: [4, 2048, 16, 121, 3] f32   (~190 MB)
// img_gt:   [2048, 16, 121, 3] f32      (~47.6 MB)
// out:      [4, 2048, 16] f32
//
// R13 left DRAM at 74%: co-resident blocks self-synchronize (TMAs complete
// together -> all compute with zero bytes in flight). R14: grid=444 blocks
// (148 SMs x 3), each owns ~18 tiles (tile = 4 (n,p) rows) with TWO tile
// buffers in dynamic smem (59.5 KB). Prologue issues tiles 0,1; iteration
// it consumes buffer it&1 via per-stream mbarrier parity waits (parity =
// (it>>1)&1), one __syncthreads marks the buffer free, tid0 issues tile
// it+2 into it, and the register-only reduction/epilogue overlaps those
// fresh loads. Loads are ALWAYS in flight during compute. Compute = R13:
// register gt cache, f32x2 packed stats, bit-16 fold + 16-lane butterfly.

#define NN       2048
#define NP       16
#define ROW      363                       // 121 patches * 3 channels
#define VSTRIDE  ((size_t)NN * NP * ROW)   // floats per view
#define NTILE    ((NN * NP) / 4)           // 8192 tiles, 4 rows each
#define CHUNK    (4 * ROW)                 // 1452 floats per stream
#define CHUNKB   (CHUNK * 4)               // 5808 bytes (16B multiple)
#define ARRF     1488                      // slot floats (5952B, 16B mult)
#define GRIDB    444                       // 148 SMs x 3 blocks
#define DYNB     (10 * ARRF * 4)           // 59520 B dynamic smem

using ull = unsigned long long;

__device__ __forceinline__ uint32_t s2u(const void* p) {
    return (uint32_t)__cvta_generic_to_shared(p);
}
__device__ __forceinline__ void mbar_init(uint32_t a, uint32_t cnt) {
    asm volatile("mbarrier.init.shared.b64 [%0], %1;" :: "r"(a), "r"(cnt) : "memory");
}
__device__ __forceinline__ void mbar_expect_tx(uint32_t a, uint32_t bytes) {
    asm volatile("mbarrier.arrive.expect_tx.shared.b64 _, [%0], %1;"
                 :: "r"(a), "r"(bytes) : "memory");
}
__device__ __forceinline__ void bulk_g2s(uint32_t dst, const void* src,
                                         uint32_t bytes, uint32_t mbar) {
    asm volatile(
        "cp.async.bulk.shared::cta.global.mbarrier::complete_tx::bytes "
        "[%0], [%1], %2, [%3];"
        :: "r"(dst), "l"(src), "r"(bytes), "r"(mbar) : "memory");
}
__device__ __forceinline__ void mbar_wait(uint32_t a, uint32_t parity) {
    uint32_t done = 0;
    while (!done) {
        asm volatile(
            "{\n\t.reg .pred p;\n\t"
            "mbarrier.try_wait.parity.acquire.cta.shared::cta.b64 p, [%1], %2, 0x989680;\n\t"
            "selp.b32 %0, 1, 0, p;\n\t}"
            : "=r"(done) : "r"(a), "r"(parity) : "memory");
    }
}
__device__ __forceinline__ ull pk2(float lo, float hi) {
    ull r; asm("mov.b64 %0, {%1, %2};" : "=l"(r) : "f"(lo), "f"(hi)); return r;
}
__device__ __forceinline__ void up2(ull v, float& lo, float& hi) {
    asm("mov.b64 {%0, %1}, %2;" : "=f"(lo), "=f"(hi) : "l"(v));
}
__device__ __forceinline__ ull fma2_(ull a, ull b, ull c) {
    ull d; asm("fma.rn.f32x2 %0, %1, %2, %3;" : "=l"(d) : "l"(a), "l"(b), "l"(c)); return d;
}
__device__ __forceinline__ ull mul2_(ull a, ull b) {
    ull d; asm("mul.rn.f32x2 %0, %1, %2;" : "=l"(d) : "l"(a), "l"(b)); return d;
}
__device__ __forceinline__ ull add2_(ull a, ull b) {
    ull d; asm("add.rn.f32x2 %0, %1, %2;" : "=l"(d) : "l"(a), "l"(b)); return d;
}

__global__ __launch_bounds__(128) void ssim_kernel(
    const float* __restrict__ pred,
    const float* __restrict__ gt,
    float* __restrict__ out)
{
    extern __shared__ __align__(16) float dyn[];   // [10][ARRF]: (buf,stream)
    __shared__ __align__(8) ull mfull[10];         // mbar per (buf,stream)
    __shared__ float sW[128];                      // per-patch weights

    const int tid  = threadIdx.x;
    const int wid  = tid >> 5;
    const int lane = tid & 31;
    const int t0   = blockIdx.x;

    #define ARR(b, s) (dyn + ((b) * 5 + (s)) * ARRF)

    // ---- tid 0: init mbarriers, fence, issue tiles for it=0 and it=1 ----
    if (tid == 0) {
        #pragma unroll
        for (int s = 0; s < 10; s++) mbar_init(s2u(&mfull[s]), 1);
        asm volatile("fence.proxy.async.shared::cta;" ::: "memory");

        #pragma unroll
        for (int it = 0; it < 2; it++) {
            const int tl = t0 + it * GRIDB;
            if (tl < NTILE) {
                const size_t off = (size_t)tl * CHUNK;
                mbar_expect_tx(s2u(&mfull[it * 5 + 0]), CHUNKB);
                bulk_g2s(s2u(ARR(it, 0)), gt + off, CHUNKB, s2u(&mfull[it * 5 + 0]));
                #pragma unroll
                for (int v = 0; v < 4; v++) {
                    mbar_expect_tx(s2u(&mfull[it * 5 + 1 + v]), CHUNKB);
                    bulk_g2s(s2u(ARR(it, 1 + v)), pred + v * VSTRIDE + off,
                             CHUNKB, s2u(&mfull[it * 5 + 1 + v]));
                }
            }
        }
    }

    // ---- concurrently: zero all slot pads, build weight table (1 expf) ----
    for (int i = tid; i < 10 * (ARRF - CHUNK); i += 128) {
        const int a = i / (ARRF - CHUNK);
        const int o = i - a * (ARRF - CHUNK);
        dyn[a * ARRF + CHUNK + o] = 0.f;
    }
    {
        const float inv2s2 = 1.0f / 4.5f;          // 1/(2*sigma^2), sigma=1.5
        const float invS2  = 0.07076226f;          // 1/S^2, S = sum of 1-D gaussian
        float w = 0.f;
        if (tid < 121) {
            int py = tid / 11, px = tid % 11;
            float dy = (float)(py - 5), dx = (float)(px - 5);
            w = expf(-(dy * dy + dx * dx) * inv2s2) * invS2;
        }
        sW[tid] = w;                               // 0 for pad patches 121..127
    }
    __syncthreads();   // publishes mbarrier init, sW, pads

    float wk[4];  ull wkp[4];
    #pragma unroll
    for (int k = 0; k < 4; k++) {
        wk[k]  = sW[k * 32 + lane];
        wkp[k] = pk2(wk[k], wk[k]);
    }

    const int wbase = wid * ROW;
    const float C1 = 1e-4f;   // 0.01^2
    const float C2 = 9e-4f;   // 0.03^2

    for (int it = 0; ; it++) {
        const int tl = t0 + it * GRIDB;
        if (tl >= NTILE) break;
        const int b = it & 1;
        const uint32_t par = (uint32_t)((it >> 1) & 1);

        // Accumulators: channels (0,1) packed, channel 2 scalar.
        ull  m1p[4], q2p[4], pgp[4];
        float m1s[4], q2s[4], pgs[4];
        ull  m2p = 0, g2p = 0;
        float m2s = 0.f, g2s = 0.f;
        #pragma unroll
        for (int v = 0; v < 4; v++) {
            m1p[v] = 0; q2p[v] = 0; pgp[v] = 0;
            m1s[v] = 0.f; q2s[v] = 0.f; pgs[v] = 0.f;
        }
        ull   bcp[4];    // cached gt (ch0,ch1) per k
        float bcs[4];    // cached gt ch2 per k

        // ---- gt phase ----
        mbar_wait(s2u(&mfull[b * 5 + 0]), par);
        {
            const float* __restrict__ B = ARR(b, 0) + wbase;
            #pragma unroll
            for (int k = 0; k < 4; k++) {
                const int base = 3 * (k * 32 + lane);
                const float b0 = B[base + 0];
                const float b1 = B[base + 1];
                const float b2 = B[base + 2];
                const ull bp = pk2(b0, b1);
                bcp[k] = bp;  bcs[k] = b2;
                const ull wbp = mul2_(wkp[k], bp);
                m2p = add2_(m2p, wbp);
                g2p = fma2_(wbp, bp, g2p);
                const float wb2 = wk[k] * b2;
                m2s += wb2;
                g2s = fmaf(wb2, b2, g2s);
            }
        }

        // ---- view phases: warp-autonomous per-stream waits ----
        #pragma unroll
        for (int v = 0; v < 4; v++) {
            mbar_wait(s2u(&mfull[b * 5 + 1 + v]), par);
            const float* __restrict__ A = ARR(b, 1 + v) + wbase;
            #pragma unroll
            for (int k = 0; k < 4; k++) {
                const int base = 3 * (k * 32 + lane);
                const float a0 = A[base + 0];
                const float a1 = A[base + 1];
                const float a2 = A[base + 2];
                const ull ap = pk2(a0, a1);
                const ull wa = mul2_(wkp[k], ap);
                m1p[v] = add2_(m1p[v], wa);
                q2p[v] = fma2_(wa, ap, q2p[v]);
                pgp[v] = fma2_(wa, bcp[k], pgp[v]);
                const float wa2 = wk[k] * a2;
                m1s[v] += wa2;
                q2s[v] = fmaf(wa2, a2, q2s[v]);
                pgs[v] = fmaf(wa2, bcs[k], pgs[v]);
            }
        }

        // ---- buffer b fully consumed: refill it with tile it+2 ----
        __syncthreads();
        if (tid == 0) {
            const int tn = tl + 2 * GRIDB;
            if (tn < NTILE) {
                const size_t off = (size_t)tn * CHUNK;
                mbar_expect_tx(s2u(&mfull[b * 5 + 0]), CHUNKB);
                bulk_g2s(s2u(ARR(b, 0)), gt + off, CHUNKB, s2u(&mfull[b * 5 + 0]));
                #pragma unroll
                for (int v = 0; v < 4; v++) {
                    mbar_expect_tx(s2u(&mfull[b * 5 + 1 + v]), CHUNKB);
                    bulk_g2s(s2u(ARR(b, 1 + v)), pred + v * VSTRIDE + off,
                             CHUNKB, s2u(&mfull[b * 5 + 1 + v]));
                }
            }
        }

        // ---- register-only reduction + epilogue (overlaps fresh loads) ----
        float M1[4][3], Q2[4][3], PG[4][3], M2[3], G2[3];
        #pragma unroll
        for (int v = 0; v < 4; v++) {
            up2(m1p[v], M1[v][0], M1[v][1]);  M1[v][2] = m1s[v];
            up2(q2p[v], Q2[v][0], Q2[v][1]);  Q2[v][2] = q2s[v];
            up2(pgp[v], PG[v][0], PG[v][1]);  PG[v][2] = pgs[v];
        }
        up2(m2p, M2[0], M2[1]);  M2[2] = m2s;
        up2(g2p, G2[0], G2[1]);  G2[2] = g2s;

        const bool hi = (lane & 16) != 0;
        float val[24];
        #pragma unroll
        for (int c = 0; c < 3; c++) {
            float kA, kB;
            #define FOLD(slotA, slotB, idx) \
                kA = (slotA); kB = (slotB); \
                { float keep = hi ? kB : kA; float send = hi ? kA : kB; \
                  val[idx] = keep + __shfl_xor_sync(0xFFFFFFFFu, send, 16); }
            FOLD(M1[0][c], M1[2][c], 0 + c);
            FOLD(Q2[0][c], Q2[2][c], 3 + c);
            FOLD(PG[0][c], PG[2][c], 6 + c);
            FOLD(M1[1][c], M1[3][c], 9 + c);
            FOLD(Q2[1][c], Q2[3][c], 12 + c);
            FOLD(PG[1][c], PG[3][c], 15 + c);
            FOLD(M2[c],    M2[c],    18 + c);   // single copy -> both halves get total
            FOLD(G2[c],    G2[c],    21 + c);
            #undef FOLD
        }
        #pragma unroll
        for (int off = 8; off; off >>= 1) {
            #pragma unroll
            for (int i = 0; i < 24; i++)
                val[i] += __shfl_xor_sync(0xFFFFFFFFu, val[i], off);
        }

        float ssim_lo = 0.f, ssim_hi_v = 0.f;
        #pragma unroll
        for (int c = 0; c < 3; c++) {
            float mu2  = val[18 + c];
            float mu2sq = mu2 * mu2;
            float s2   = val[21 + c] - mu2sq;
            {   // view lo
                float mu1 = val[0 + c];
                float mu1sq = mu1 * mu1;
                float mu12  = mu1 * mu2;
                float s1  = val[3 + c] - mu1sq;
                float s12 = val[6 + c] - mu12;
                float num = (2.0f * mu12 + C1) * (2.0f * s12 + C2);
                float den = (mu1sq + mu2sq + C1) * (s1 + s2 + C2);
                ssim_lo += __fdividef(num, den);
            }
            {   // view hi
                float mu1 = val[9 + c];
                float mu1sq = mu1 * mu1;
                float mu12  = mu1 * mu2;
                float s1  = val[12 + c] - mu1sq;
                float s12 = val[15 + c] - mu12;
                float num = (2.0f * mu12 + C1) * (2.0f * s12 + C2);
                float den = (mu1sq + mu2sq + C1) * (s1 + s2 + C2);
                ssim_hi_v += __fdividef(num, den);
            }
        }

        // Writers: lanes 0,1 (views 0,1) and 16,17 (views 2,3).
        if ((lane & 14) == 0) {
            const int q = tl * 4 + wid;          // global (n,p) row
            const int n = q >> 4;
            const int p = q & 15;
            int sel  = lane & 1;
            int view = ((lane >> 4) << 1) | sel;
            float res = (sel ? ssim_hi_v : ssim_lo) * (1.0f / 3.0f);
            out[(view * NN + n) * NP + p] = res;
        }
    }
    #undef ARR
}

extern "C" void kernel_launch(void* const* d_in, const int* in_sizes, int n_in,
                              void* d_out, int out_size)
{
    const float* pred = (const float*)d_in[0];   // img_pred [4,2048,16,121,3]
    const float* gt   = (const float*)d_in[1];   // img_gt   [2048,16,121,3]
    float* out = (float*)d_out;                  // [4,2048,16]

    cudaFuncSetAttribute(ssim_kernel,
                         cudaFuncAttributeMaxDynamicSharedMemorySize, DYNB);
    ssim_kernel<<<GRIDB, 128, DYNB>>>(pred, gt, out);
}